// round 1
// baseline (speedup 1.0000x reference)
#include <cuda_runtime.h>
#include <float.h>
#include <math.h>

#define S_LEN  4096
#define D_MODEL 1024
#define NH     16
#define DK     64
#define DKV    256
#define ATT_SCALE 0.125f   // 1/sqrt(64)

// -------- scratch (device globals; no allocation allowed) --------
__device__ float g_Q[S_LEN * D_MODEL];   // [S, H*DK]
__device__ float g_K[S_LEN * DKV];       // [S, HKV*DK]
__device__ float g_V[S_LEN * DKV];
__device__ float g_O[S_LEN * D_MODEL];   // attention output [S, H*DK]
__device__ unsigned char g_mask[S_LEN];

// ---------------------------------------------------------------------------
// Mask canonicalization: the harness may deliver the jax bool mask as
// bool(1B) / int32 / float32. Detect from the first 4096 bytes (safe for all
// encodings) and expand to uint8.
// ---------------------------------------------------------------------------
__global__ void mask_detect_expand_kernel(const unsigned char* __restrict__ p, int n) {
    __shared__ int not_int, not_float;
    if (threadIdx.x == 0) { not_int = 0; not_float = 0; }
    __syncthreads();
    // inspect first n bytes (n == 4096; smallest possible allocation)
    for (int j = threadIdx.x; j < n; j += blockDim.x) {
        unsigned char v = p[j];
        int r = j & 3;
        bool ok_int = (r == 0) ? (v <= 1) : (v == 0);
        bool ok_float = (r == 3) ? (v == 0 || v == 0x3F)
                      : (r == 2) ? (v == 0 || v == 0x80)
                      : (v == 0);
        if (!ok_int)   atomicOr(&not_int, 1);
        if (!ok_float) atomicOr(&not_float, 1);
    }
    __syncthreads();
    int mode = (!not_int) ? 0 : ((!not_float) ? 1 : 2); // 0=int32,1=float32,2=bool
    for (int i = threadIdx.x; i < n; i += blockDim.x) {
        unsigned char m;
        if (mode == 0)      m = (((const int*)p)[i]   != 0);
        else if (mode == 1) m = (((const float*)p)[i] != 0.0f);
        else                m = (p[i] != 0);
        g_mask[i] = m;
    }
}

// ---------------------------------------------------------------------------
// C[M,N] = A[M,K] @ W[K,N] + bias    (64x64 tile, BK=16, 4x4 micro tile)
// ---------------------------------------------------------------------------
__global__ __launch_bounds__(256) void sgemm_bias_kernel(
    const float* __restrict__ A, const float* __restrict__ W,
    const float* __restrict__ bias, float* __restrict__ C,
    int M, int N, int K)
{
    __shared__ float As[16][68];  // As[k][m]
    __shared__ float Ws[16][68];  // Ws[k][n]
    int tid = threadIdx.x;
    int tx = tid & 15, ty = tid >> 4;
    int r0 = blockIdx.y * 64, c0 = blockIdx.x * 64;

    float acc[4][4] = {};
    int la_r = tid >> 2;            // 0..63 (m)
    int la_c = (tid & 3) * 4;       // 0..12 (k)
    int lw_r = tid >> 4;            // 0..15 (k)
    int lw_c = (tid & 15) * 4;      // 0..60 (n)

    for (int k0 = 0; k0 < K; k0 += 16) {
        float4 a4 = *(const float4*)&A[(size_t)(r0 + la_r) * K + k0 + la_c];
        As[la_c + 0][la_r] = a4.x;
        As[la_c + 1][la_r] = a4.y;
        As[la_c + 2][la_r] = a4.z;
        As[la_c + 3][la_r] = a4.w;
        *(float4*)&Ws[lw_r][lw_c] =
            *(const float4*)&W[(size_t)(k0 + lw_r) * N + c0 + lw_c];
        __syncthreads();
        #pragma unroll
        for (int k = 0; k < 16; k++) {
            float4 a = *(const float4*)&As[k][ty * 4];
            float4 b = *(const float4*)&Ws[k][tx * 4];
            float av[4] = {a.x, a.y, a.z, a.w};
            float bv[4] = {b.x, b.y, b.z, b.w};
            #pragma unroll
            for (int m = 0; m < 4; m++)
                #pragma unroll
                for (int n = 0; n < 4; n++)
                    acc[m][n] += av[m] * bv[n];
        }
        __syncthreads();
    }
    #pragma unroll
    for (int m = 0; m < 4; m++) {
        int row = r0 + ty * 4 + m;
        #pragma unroll
        for (int n = 0; n < 4; n++) {
            int col = c0 + tx * 4 + n;
            C[(size_t)row * N + col] = acc[m][n] + bias[col];
        }
    }
}

// ---------------------------------------------------------------------------
// Flash attention: one block = 64 queries x one head. Loops 64-key tiles.
// Online softmax with finite -FLT_MAX masking (matches reference finfo.min).
// ---------------------------------------------------------------------------
#define ATT_SMEM_FLOATS (64*68*3 + 64*65)
__global__ __launch_bounds__(256) void flash_attn_kernel(
    const float* __restrict__ Q, const float* __restrict__ K,
    const float* __restrict__ V, float* __restrict__ O)
{
    extern __shared__ float sm[];
    float* qs = sm;               // [d][q] 64x68
    float* ks = qs + 64 * 68;     // [d][t] 64x68
    float* vs = ks + 64 * 68;     // [t][d] 64x68
    float* ps = vs + 64 * 68;     // [q][t] 64x65

    int tid = threadIdx.x;
    int tx = tid & 15, ty = tid >> 4;
    int h  = blockIdx.y;
    int s0 = blockIdx.x * 64;
    int kv = h >> 2;              // kv head = h / G

    const float* Qb = Q + (size_t)s0 * D_MODEL + h * DK;

    int lr = tid >> 2;            // row (q or t) 0..63
    int dbase = (tid & 3) * 4;    // 0..12

    // load Q tile transposed (qs[d][q])
    #pragma unroll
    for (int p = 0; p < 4; p++) {
        int d = dbase + p * 16;
        float4 v4 = *(const float4*)&Qb[(size_t)lr * D_MODEL + d];
        qs[(d + 0) * 68 + lr] = v4.x;
        qs[(d + 1) * 68 + lr] = v4.y;
        qs[(d + 2) * 68 + lr] = v4.z;
        qs[(d + 3) * 68 + lr] = v4.w;
    }

    float m_i[4], l_i[4], acc[4][4];
    #pragma unroll
    for (int m = 0; m < 4; m++) {
        m_i[m] = -FLT_MAX; l_i[m] = 0.f;
        #pragma unroll
        for (int n = 0; n < 4; n++) acc[m][n] = 0.f;
    }
    __syncthreads();

    for (int t0 = 0; t0 < S_LEN; t0 += 64) {
        const float* Kb = K + (size_t)t0 * DKV + kv * DK;
        const float* Vb = V + (size_t)t0 * DKV + kv * DK;
        #pragma unroll
        for (int p = 0; p < 4; p++) {
            int d = dbase + p * 16;
            float4 k4 = *(const float4*)&Kb[(size_t)lr * DKV + d];
            ks[(d + 0) * 68 + lr] = k4.x;
            ks[(d + 1) * 68 + lr] = k4.y;
            ks[(d + 2) * 68 + lr] = k4.z;
            ks[(d + 3) * 68 + lr] = k4.w;
            *(float4*)&vs[lr * 68 + d] = *(const float4*)&Vb[(size_t)lr * DKV + d];
        }
        __syncthreads();

        // S = Q K^T  (64x64x64)
        float s[4][4] = {};
        #pragma unroll 8
        for (int d = 0; d < 64; d++) {
            float4 a = *(const float4*)&qs[d * 68 + ty * 4];
            float4 b = *(const float4*)&ks[d * 68 + tx * 4];
            float av[4] = {a.x, a.y, a.z, a.w};
            float bv[4] = {b.x, b.y, b.z, b.w};
            #pragma unroll
            for (int m = 0; m < 4; m++)
                #pragma unroll
                for (int n = 0; n < 4; n++)
                    s[m][n] += av[m] * bv[n];
        }

        // scale + mask (finite min, matching reference)
        unsigned char mk[4];
        #pragma unroll
        for (int n = 0; n < 4; n++) mk[n] = g_mask[t0 + tx * 4 + n];
        #pragma unroll
        for (int m = 0; m < 4; m++)
            #pragma unroll
            for (int n = 0; n < 4; n++)
                s[m][n] = mk[n] ? -FLT_MAX : s[m][n] * ATT_SCALE;

        // online softmax update
        #pragma unroll
        for (int m = 0; m < 4; m++) {
            float rmax = fmaxf(fmaxf(s[m][0], s[m][1]), fmaxf(s[m][2], s[m][3]));
            #pragma unroll
            for (int off = 8; off >= 1; off >>= 1)
                rmax = fmaxf(rmax, __shfl_xor_sync(0xffffffffu, rmax, off));
            float mnew = fmaxf(m_i[m], rmax);
            float corr = __expf(m_i[m] - mnew);
            float rsum = 0.f;
            #pragma unroll
            for (int n = 0; n < 4; n++) {
                float pv = __expf(s[m][n] - mnew);
                s[m][n] = pv;           // reuse as P
                rsum += pv;
            }
            #pragma unroll
            for (int off = 8; off >= 1; off >>= 1)
                rsum += __shfl_xor_sync(0xffffffffu, rsum, off);
            l_i[m] = l_i[m] * corr + rsum;
            m_i[m] = mnew;
            #pragma unroll
            for (int n = 0; n < 4; n++) acc[m][n] *= corr;
        }

        // stage P
        #pragma unroll
        for (int m = 0; m < 4; m++)
            #pragma unroll
            for (int n = 0; n < 4; n++)
                ps[(ty * 4 + m) * 65 + tx * 4 + n] = s[m][n];
        __syncthreads();

        // O += P @ V
        #pragma unroll 4
        for (int t = 0; t < 64; t++) {
            float4 v = *(const float4*)&vs[t * 68 + tx * 4];
            float vv[4] = {v.x, v.y, v.z, v.w};
            float pm[4];
            #pragma unroll
            for (int m = 0; m < 4; m++) pm[m] = ps[(ty * 4 + m) * 65 + t];
            #pragma unroll
            for (int m = 0; m < 4; m++)
                #pragma unroll
                for (int n = 0; n < 4; n++)
                    acc[m][n] += pm[m] * vv[n];
        }
        __syncthreads();
    }

    #pragma unroll
    for (int m = 0; m < 4; m++) {
        float inv = 1.f / l_i[m];
        int row = s0 + ty * 4 + m;
        #pragma unroll
        for (int n = 0; n < 4; n++)
            O[(size_t)row * D_MODEL + h * DK + tx * 4 + n] = acc[m][n] * inv;
    }
}

// ---------------------------------------------------------------------------
extern "C" void kernel_launch(void* const* d_in, const int* in_sizes, int n_in,
                              void* d_out, int out_size) {
    const float* x   = (const float*)d_in[0];
    const unsigned char* mask = (const unsigned char*)d_in[1];
    const float* Wq  = (const float*)d_in[2];
    const float* bq  = (const float*)d_in[3];
    const float* Wk  = (const float*)d_in[4];
    const float* bk  = (const float*)d_in[5];
    const float* Wv  = (const float*)d_in[6];
    const float* bv  = (const float*)d_in[7];
    const float* Wo  = (const float*)d_in[8];
    const float* bo  = (const float*)d_in[9];
    float* out = (float*)d_out;

    float *pQ, *pK, *pV, *pO;
    cudaGetSymbolAddress((void**)&pQ, g_Q);
    cudaGetSymbolAddress((void**)&pK, g_K);
    cudaGetSymbolAddress((void**)&pV, g_V);
    cudaGetSymbolAddress((void**)&pO, g_O);

    // 1. mask canonicalization
    mask_detect_expand_kernel<<<1, 256>>>(mask, S_LEN);

    // 2. projections
    sgemm_bias_kernel<<<dim3(D_MODEL / 64, S_LEN / 64), 256>>>(x, Wq, bq, pQ, S_LEN, D_MODEL, D_MODEL);
    sgemm_bias_kernel<<<dim3(DKV / 64,    S_LEN / 64), 256>>>(x, Wk, bk, pK, S_LEN, DKV, D_MODEL);
    sgemm_bias_kernel<<<dim3(DKV / 64,    S_LEN / 64), 256>>>(x, Wv, bv, pV, S_LEN, DKV, D_MODEL);

    // 3. attention
    static bool attr_set = false;
    size_t smem = ATT_SMEM_FLOATS * sizeof(float);
    if (!attr_set) {
        cudaFuncSetAttribute(flash_attn_kernel,
                             cudaFuncAttributeMaxDynamicSharedMemorySize, (int)smem);
        attr_set = true;
    }
    flash_attn_kernel<<<dim3(S_LEN / 64, NH), 256, smem>>>(pQ, pK, pV, pO);

    // 4. output projection
    sgemm_bias_kernel<<<dim3(D_MODEL / 64, S_LEN / 64), 256>>>(pO, Wo, bo, out, S_LEN, D_MODEL, D_MODEL);
}

// round 2
// speedup vs baseline: 1.0029x; 1.0029x over previous
#include <cuda_runtime.h>
#include <mma.h>
#include <float.h>
#include <math.h>

using namespace nvcuda;

#define S_LEN   4096
#define D_MODEL 1024
#define NH      16
#define DK      64
#define DKV     256
#define ATT_SCALE 0.125f   // 1/sqrt(64)

// -------- scratch (device globals; no allocation allowed) --------
__device__ float g_Q[S_LEN * D_MODEL];
__device__ float g_K[S_LEN * DKV];
__device__ float g_V[S_LEN * DKV];
__device__ float g_O[S_LEN * D_MODEL];
__device__ unsigned char g_mask[S_LEN];

// ---------------------------------------------------------------------------
// Mask canonicalization (bool / int32 / float32 -> uint8)
// ---------------------------------------------------------------------------
__global__ void mask_detect_expand_kernel(const unsigned char* __restrict__ p, int n) {
    __shared__ int not_int, not_float;
    if (threadIdx.x == 0) { not_int = 0; not_float = 0; }
    __syncthreads();
    for (int j = threadIdx.x; j < n; j += blockDim.x) {
        unsigned char v = p[j];
        int r = j & 3;
        bool ok_int = (r == 0) ? (v <= 1) : (v == 0);
        bool ok_float = (r == 3) ? (v == 0 || v == 0x3F)
                      : (r == 2) ? (v == 0 || v == 0x80)
                      : (v == 0);
        if (!ok_int)   atomicOr(&not_int, 1);
        if (!ok_float) atomicOr(&not_float, 1);
    }
    __syncthreads();
    int mode = (!not_int) ? 0 : ((!not_float) ? 1 : 2);
    for (int i = threadIdx.x; i < n; i += blockDim.x) {
        unsigned char m;
        if (mode == 0)      m = (((const int*)p)[i]   != 0);
        else if (mode == 1) m = (((const float*)p)[i] != 0.0f);
        else                m = (p[i] != 0);
        g_mask[i] = m;
    }
}

// ---------------------------------------------------------------------------
// TF32 GEMM: C[M,N] = A[M,K] @ W[K,N] + bias
// Block tile 128x64, BK=32. 8 warps in 4x2; warp tile 32x32 (2x2 wmma frags).
// ---------------------------------------------------------------------------
#define GA_LDM 40
#define GB_LDM 72
#define GC_LDM 72
#define GEMM_SMEM_BYTES (128 * GC_LDM * 4)   // 36864; >= As+Bs (29696)

__global__ __launch_bounds__(256) void gemm_tf32_kernel(
    const float* __restrict__ A, const float* __restrict__ W,
    const float* __restrict__ bias, float* __restrict__ C,
    int M, int N, int K)
{
    extern __shared__ float sm[];
    float* As = sm;                      // [128][40]
    float* Bs = sm + 128 * GA_LDM;       // [32][72]
    float* Cs = sm;                      // [128][72] reused after compute

    int tid  = threadIdx.x;
    int warp = tid >> 5;
    int wm   = warp >> 1;                // 0..3
    int wn   = warp & 1;                 // 0..1
    int r0 = blockIdx.y * 128, c0 = blockIdx.x * 64;

    wmma::fragment<wmma::accumulator, 16, 16, 8, float> acc[2][2];
    #pragma unroll
    for (int i = 0; i < 2; i++)
        #pragma unroll
        for (int j = 0; j < 2; j++) wmma::fill_fragment(acc[i][j], 0.f);

    int a_row = tid >> 3;                // 0..31 (x4 strided 32)
    int a_col = (tid & 7) * 4;
    int b_row = tid >> 4;                // 0..15 (x2 strided 16)
    int b_col = (tid & 15) * 4;

    for (int k0 = 0; k0 < K; k0 += 32) {
        #pragma unroll
        for (int i = 0; i < 4; i++) {
            int r = a_row + i * 32;
            *(float4*)&As[r * GA_LDM + a_col] =
                *(const float4*)&A[(size_t)(r0 + r) * K + k0 + a_col];
        }
        #pragma unroll
        for (int i = 0; i < 2; i++) {
            int r = b_row + i * 16;
            *(float4*)&Bs[r * GB_LDM + b_col] =
                *(const float4*)&W[(size_t)(k0 + r) * N + c0 + b_col];
        }
        __syncthreads();
        #pragma unroll
        for (int kk = 0; kk < 32; kk += 8) {
            wmma::fragment<wmma::matrix_a, 16, 16, 8, wmma::precision::tf32, wmma::row_major> af[2];
            wmma::fragment<wmma::matrix_b, 16, 16, 8, wmma::precision::tf32, wmma::row_major> bf[2];
            #pragma unroll
            for (int i = 0; i < 2; i++) {
                wmma::load_matrix_sync(af[i], &As[(wm * 32 + i * 16) * GA_LDM + kk], GA_LDM);
                #pragma unroll
                for (int t = 0; t < af[i].num_elements; t++)
                    af[i].x[t] = wmma::__float_to_tf32(af[i].x[t]);
            }
            #pragma unroll
            for (int j = 0; j < 2; j++) {
                wmma::load_matrix_sync(bf[j], &Bs[kk * GB_LDM + wn * 32 + j * 16], GB_LDM);
                #pragma unroll
                for (int t = 0; t < bf[j].num_elements; t++)
                    bf[j].x[t] = wmma::__float_to_tf32(bf[j].x[t]);
            }
            #pragma unroll
            for (int i = 0; i < 2; i++)
                #pragma unroll
                for (int j = 0; j < 2; j++)
                    wmma::mma_sync(acc[i][j], af[i], bf[j], acc[i][j]);
        }
        __syncthreads();
    }

    #pragma unroll
    for (int i = 0; i < 2; i++)
        #pragma unroll
        for (int j = 0; j < 2; j++)
            wmma::store_matrix_sync(&Cs[(wm * 32 + i * 16) * GC_LDM + wn * 32 + j * 16],
                                    acc[i][j], GC_LDM, wmma::mem_row_major);
    __syncthreads();

    int c_col = (tid & 15) * 4;
    float4 b4 = *(const float4*)&bias[c0 + c_col];
    #pragma unroll
    for (int i = 0; i < 8; i++) {
        int r = (tid >> 4) + i * 16;
        float4 v = *(float4*)&Cs[r * GC_LDM + c_col];
        v.x += b4.x; v.y += b4.y; v.z += b4.z; v.w += b4.w;
        *(float4*)&C[(size_t)(r0 + r) * N + c0 + c_col] = v;
    }
}

// ---------------------------------------------------------------------------
// TF32 flash attention: block = 64 queries x one head; 64-key tiles.
// O accumulator lives in smem (rescaled scalar-side); PV accumulates into it
// via wmma accumulator load/store.
// ---------------------------------------------------------------------------
#define A_LDM 72
#define ATT_SMEM_FLOATS (5 * 64 * A_LDM + 2 * 64)
__global__ __launch_bounds__(256) void flash_attn_tf32_kernel(
    const float* __restrict__ Q, const float* __restrict__ K,
    const float* __restrict__ V, float* __restrict__ O)
{
    extern __shared__ float sm[];
    float* Qs = sm;                  // [64][72] row-major [q][d]
    float* Ks = Qs + 64 * A_LDM;     // [64][72] row-major [t][d]
    float* Vs = Ks + 64 * A_LDM;     // [64][72] row-major [t][d]
    float* Ss = Vs + 64 * A_LDM;     // [64][72] scores / P [q][t]
    float* Os = Ss + 64 * A_LDM;     // [64][72] O accumulator [q][d]
    float* m_s = Os + 64 * A_LDM;    // [64]
    float* l_s = m_s + 64;           // [64]

    int tid  = threadIdx.x;
    int warp = tid >> 5;
    int wm   = warp >> 1;            // 0..3 -> 16-row slice
    int wn   = warp & 1;             // 0..1 -> 32-col slice
    int h    = blockIdx.y;
    int s0   = blockIdx.x * 64;
    int kv   = h >> 2;

    int row   = tid >> 2;            // 0..63
    int lane4 = tid & 3;             // 4 lanes per row
    int cbase = lane4 * 16;

    // load Q tile, init O/m/l
    {
        const float* Qb = Q + (size_t)(s0 + row) * D_MODEL + h * DK;
        #pragma unroll
        for (int j = 0; j < 4; j++) {
            *(float4*)&Qs[row * A_LDM + cbase + j * 4] = *(const float4*)&Qb[cbase + j * 4];
            *(float4*)&Os[row * A_LDM + cbase + j * 4] = make_float4(0.f, 0.f, 0.f, 0.f);
        }
        if (tid < 64) { m_s[tid] = -FLT_MAX; l_s[tid] = 0.f; }
    }
    __syncthreads();

    for (int t0 = 0; t0 < S_LEN; t0 += 64) {
        // load K, V tiles
        {
            const float* Kb = K + (size_t)(t0 + row) * DKV + kv * DK;
            const float* Vb = V + (size_t)(t0 + row) * DKV + kv * DK;
            #pragma unroll
            for (int j = 0; j < 4; j++) {
                *(float4*)&Ks[row * A_LDM + cbase + j * 4] = *(const float4*)&Kb[cbase + j * 4];
                *(float4*)&Vs[row * A_LDM + cbase + j * 4] = *(const float4*)&Vb[cbase + j * 4];
            }
        }
        __syncthreads();

        // S = Q @ K^T  (64x64x64)
        {
            wmma::fragment<wmma::accumulator, 16, 16, 8, float> sacc[2];
            #pragma unroll
            for (int j = 0; j < 2; j++) wmma::fill_fragment(sacc[j], 0.f);
            #pragma unroll
            for (int kk = 0; kk < 64; kk += 8) {
                wmma::fragment<wmma::matrix_a, 16, 16, 8, wmma::precision::tf32, wmma::row_major> af;
                wmma::load_matrix_sync(af, &Qs[(wm * 16) * A_LDM + kk], A_LDM);
                #pragma unroll
                for (int t = 0; t < af.num_elements; t++) af.x[t] = wmma::__float_to_tf32(af.x[t]);
                #pragma unroll
                for (int j = 0; j < 2; j++) {
                    wmma::fragment<wmma::matrix_b, 16, 16, 8, wmma::precision::tf32, wmma::col_major> bf;
                    // element (k=d, n=t) at Ks[t*A_LDM + d] -> col_major ldm A_LDM
                    wmma::load_matrix_sync(bf, &Ks[(wn * 32 + j * 16) * A_LDM + kk], A_LDM);
                    #pragma unroll
                    for (int t = 0; t < bf.num_elements; t++) bf.x[t] = wmma::__float_to_tf32(bf.x[t]);
                    wmma::mma_sync(sacc[j], af, bf, sacc[j]);
                }
            }
            #pragma unroll
            for (int j = 0; j < 2; j++)
                wmma::store_matrix_sync(&Ss[(wm * 16) * A_LDM + wn * 32 + j * 16],
                                        sacc[j], A_LDM, wmma::mem_row_major);
        }
        __syncthreads();

        // online softmax (scalar; 4 lanes per row) + O rescale
        {
            float* Srow = &Ss[row * A_LDM + cbase];
            float sv[16];
            float mloc = -FLT_MAX;
            #pragma unroll
            for (int j = 0; j < 16; j++) {
                float s = Srow[j];
                s = g_mask[t0 + cbase + j] ? -FLT_MAX : s * ATT_SCALE;
                sv[j] = s;
                mloc = fmaxf(mloc, s);
            }
            mloc = fmaxf(mloc, __shfl_xor_sync(0xffffffffu, mloc, 1));
            mloc = fmaxf(mloc, __shfl_xor_sync(0xffffffffu, mloc, 2));
            float mold = m_s[row];
            float mnew = fmaxf(mold, mloc);
            float corr = __expf(mold - mnew);
            float sum = 0.f;
            #pragma unroll
            for (int j = 0; j < 16; j++) {
                float p = __expf(sv[j] - mnew);
                Srow[j] = p;
                sum += p;
            }
            sum += __shfl_xor_sync(0xffffffffu, sum, 1);
            sum += __shfl_xor_sync(0xffffffffu, sum, 2);
            if (lane4 == 0) {
                m_s[row] = mnew;
                l_s[row] = l_s[row] * corr + sum;
            }
            // rescale O accumulator rows (each lane owns 16 cols of its row)
            float* Orow = &Os[row * A_LDM + cbase];
            #pragma unroll
            for (int j = 0; j < 16; j++) Orow[j] *= corr;
        }
        __syncthreads();

        // O += P @ V  (64x64x64), accumulator in smem
        {
            wmma::fragment<wmma::accumulator, 16, 16, 8, float> oacc[2];
            #pragma unroll
            for (int j = 0; j < 2; j++)
                wmma::load_matrix_sync(oacc[j], &Os[(wm * 16) * A_LDM + wn * 32 + j * 16],
                                       A_LDM, wmma::mem_row_major);
            #pragma unroll
            for (int kk = 0; kk < 64; kk += 8) {
                wmma::fragment<wmma::matrix_a, 16, 16, 8, wmma::precision::tf32, wmma::row_major> af;
                wmma::load_matrix_sync(af, &Ss[(wm * 16) * A_LDM + kk], A_LDM);
                #pragma unroll
                for (int t = 0; t < af.num_elements; t++) af.x[t] = wmma::__float_to_tf32(af.x[t]);
                #pragma unroll
                for (int j = 0; j < 2; j++) {
                    wmma::fragment<wmma::matrix_b, 16, 16, 8, wmma::precision::tf32, wmma::row_major> bf;
                    wmma::load_matrix_sync(bf, &Vs[kk * A_LDM + wn * 32 + j * 16], A_LDM);
                    #pragma unroll
                    for (int t = 0; t < bf.num_elements; t++) bf.x[t] = wmma::__float_to_tf32(bf.x[t]);
                    wmma::mma_sync(oacc[j], af, bf, oacc[j]);
                }
            }
            #pragma unroll
            for (int j = 0; j < 2; j++)
                wmma::store_matrix_sync(&Os[(wm * 16) * A_LDM + wn * 32 + j * 16],
                                        oacc[j], A_LDM, wmma::mem_row_major);
        }
        __syncthreads();
    }

    // epilogue: normalize and write
    {
        float inv = 1.f / l_s[row];
        float* Op = O + (size_t)(s0 + row) * D_MODEL + h * DK;
        #pragma unroll
        for (int j = 0; j < 16; j++)
            Op[cbase + j] = Os[row * A_LDM + cbase + j] * inv;
    }
}

// ---------------------------------------------------------------------------
extern "C" void kernel_launch(void* const* d_in, const int* in_sizes, int n_in,
                              void* d_out, int out_size) {
    const float* x   = (const float*)d_in[0];
    const unsigned char* mask = (const unsigned char*)d_in[1];
    const float* Wq  = (const float*)d_in[2];
    const float* bq  = (const float*)d_in[3];
    const float* Wk  = (const float*)d_in[4];
    const float* bk  = (const float*)d_in[5];
    const float* Wv  = (const float*)d_in[6];
    const float* bv  = (const float*)d_in[7];
    const float* Wo  = (const float*)d_in[8];
    const float* bo  = (const float*)d_in[9];
    float* out = (float*)d_out;

    float *pQ, *pK, *pV, *pO;
    cudaGetSymbolAddress((void**)&pQ, g_Q);
    cudaGetSymbolAddress((void**)&pK, g_K);
    cudaGetSymbolAddress((void**)&pV, g_V);
    cudaGetSymbolAddress((void**)&pO, g_O);

    static bool attr_set = false;
    size_t att_smem = ATT_SMEM_FLOATS * sizeof(float);
    if (!attr_set) {
        cudaFuncSetAttribute(gemm_tf32_kernel,
                             cudaFuncAttributeMaxDynamicSharedMemorySize, GEMM_SMEM_BYTES);
        cudaFuncSetAttribute(flash_attn_tf32_kernel,
                             cudaFuncAttributeMaxDynamicSharedMemorySize, (int)att_smem);
        attr_set = true;
    }

    mask_detect_expand_kernel<<<1, 256>>>(mask, S_LEN);

    gemm_tf32_kernel<<<dim3(D_MODEL / 64, S_LEN / 128), 256, GEMM_SMEM_BYTES>>>(
        x, Wq, bq, pQ, S_LEN, D_MODEL, D_MODEL);
    gemm_tf32_kernel<<<dim3(DKV / 64, S_LEN / 128), 256, GEMM_SMEM_BYTES>>>(
        x, Wk, bk, pK, S_LEN, DKV, D_MODEL);
    gemm_tf32_kernel<<<dim3(DKV / 64, S_LEN / 128), 256, GEMM_SMEM_BYTES>>>(
        x, Wv, bv, pV, S_LEN, DKV, D_MODEL);

    flash_attn_tf32_kernel<<<dim3(S_LEN / 64, NH), 256, att_smem>>>(pQ, pK, pV, pO);

    gemm_tf32_kernel<<<dim3(D_MODEL / 64, S_LEN / 128), 256, GEMM_SMEM_BYTES>>>(
        pO, Wo, bo, out, S_LEN, D_MODEL, D_MODEL);
}